// round 7
// baseline (speedup 1.0000x reference)
#include <cuda_runtime.h>
#include <cstdint>

// Problem constants
#define B_   8
#define QL_  128
#define ML_  1024
#define KS_  512
#define H_   256

typedef unsigned long long ull;

// ---------- Blackwell packed-f32 helpers ----------
__device__ __forceinline__ ull pack2(float x, float y) {
    ull r; asm("mov.b64 %0, {%1,%2};" : "=l"(r) : "f"(x), "f"(y)); return r;
}
__device__ __forceinline__ void fma2(ull &d, ull a, ull b) {
    asm("fma.rn.f32x2 %0, %1, %2, %0;" : "+l"(d) : "l"(a), "l"(b));
}
__device__ __forceinline__ float2 unpack2(ull v) {
    float2 f; asm("mov.b64 {%0,%1}, %2;" : "=f"(f.x), "=f"(f.y) : "l"(v)); return f;
}
__device__ __forceinline__ float fast_tanh(float x) {
    float r; asm("tanh.approx.f32 %0, %1;" : "=f"(r) : "f"(x)); return r;
}
__device__ __forceinline__ void cp_async16(void* smem_dst, const void* gsrc) {
    unsigned int s = (unsigned int)__cvta_generic_to_shared(smem_dst);
    asm volatile("cp.async.ca.shared.global [%0], [%1], 16;" :: "r"(s), "l"(gsrc) : "memory");
}

// ---------- scratch ----------
__device__ float g_q[B_ * QL_ * H_];          // [B*QL][H]
__device__ float g_kT[B_ * H_ * ML_];         // [B][H][ML]
__device__ float g_wfallback[B_ * QL_ * ML_];
__device__ int   g_mask_mode;                 // 0=u8, 1=i32, 2=f32

// ---------- mask dtype auto-detection ----------
__global__ void detect_mask_kernel(const unsigned char* __restrict__ m) {
    __shared__ int viol[3];
    if (threadIdx.x < 3) viol[threadIdx.x] = 0;
    __syncthreads();
    int v_u8 = 0, v_i32 = 0, v_f32 = 0;
    for (int i = threadIdx.x; i < B_ * ML_; i += 256) {
        unsigned char b = m[i];
        int r = i & 3;
        if (b > 1) v_u8++;
        if (r != 0 && b != 0) v_i32++;
        if (r == 0 || r == 1) { if (b != 0) v_f32++; }
        else if (r == 2)      { if (b != 0 && b != 128) v_f32++; }
        else                  { if (b != 0 && b != 63)  v_f32++; }
    }
    atomicAdd(&viol[0], v_u8);
    atomicAdd(&viol[1], v_i32);
    atomicAdd(&viol[2], v_f32);
    __syncthreads();
    if (threadIdx.x == 0) {
        int mode;
        if      (viol[1] == 0) mode = 1;
        else if (viol[2] == 0) mode = 2;
        else                   mode = 0;
        g_mask_mode = mode;
    }
}

// ---------- projection GEMM: out = A[M,K] x W[N=256,K]^T + bias ----------
// Register double-buffered k-loop; kt_mode=1 does a smem-transposed coalesced
// epilogue (out[b][n][ml]) instead of scattered column stores.
#define GBM 64
#define GBN 128
#define GBK 16

__global__ __launch_bounds__(256) void gemm_bias_kernel(
    const float* __restrict__ A, const float* __restrict__ W,
    const float* __restrict__ bias, float* __restrict__ out,
    int K, int kt_mode)
{
    __shared__ float As[GBK][GBM];
    __shared__ float Ws[GBK][GBN];
    __shared__ float T[GBN][GBM + 1];   // 33.3 KB, kt epilogue staging

    const int tid = threadIdx.x;
    const int tx = tid & 15;
    const int ty = tid >> 4;
    const int m0 = blockIdx.y * GBM;
    const int n0 = blockIdx.x * GBN;

    ull acc[4][4];
#pragma unroll
    for (int i = 0; i < 4; i++)
#pragma unroll
        for (int j = 0; j < 4; j++) acc[i][j] = 0ull;

    const int arow = tid >> 2;
    const int acol = (tid & 3) << 2;

    // prefetch tile 0 into registers
    float4 av = *(const float4*)&A[(size_t)(m0 + arow) * K + acol];
    float4 w0 = *(const float4*)&W[(size_t)(n0 + arow) * K + acol];
    float4 w1 = *(const float4*)&W[(size_t)(n0 + arow + 64) * K + acol];

    for (int k0 = 0; k0 < K; k0 += GBK) {
        // store staged regs (k-major transpose in smem)
        As[acol + 0][arow] = av.x; As[acol + 1][arow] = av.y;
        As[acol + 2][arow] = av.z; As[acol + 3][arow] = av.w;
        Ws[acol + 0][arow] = w0.x; Ws[acol + 1][arow] = w0.y;
        Ws[acol + 2][arow] = w0.z; Ws[acol + 3][arow] = w0.w;
        Ws[acol + 0][arow + 64] = w1.x; Ws[acol + 1][arow + 64] = w1.y;
        Ws[acol + 2][arow + 64] = w1.z; Ws[acol + 3][arow + 64] = w1.w;
        __syncthreads();

        // prefetch next tile (overlaps with compute below)
        if (k0 + GBK < K) {
            av = *(const float4*)&A[(size_t)(m0 + arow) * K + k0 + GBK + acol];
            w0 = *(const float4*)&W[(size_t)(n0 + arow) * K + k0 + GBK + acol];
            w1 = *(const float4*)&W[(size_t)(n0 + arow + 64) * K + k0 + GBK + acol];
        }

#pragma unroll
        for (int kk = 0; kk < GBK; kk++) {
            float4 a4  = *(const float4*)&As[kk][ty << 2];
            float4 wv0 = *(const float4*)&Ws[kk][tx << 3];
            float4 wv1 = *(const float4*)&Ws[kk][(tx << 3) + 4];
            ull a2[4] = { pack2(a4.x, a4.x), pack2(a4.y, a4.y),
                          pack2(a4.z, a4.z), pack2(a4.w, a4.w) };
            ull b2[4] = { pack2(wv0.x, wv0.y), pack2(wv0.z, wv0.w),
                          pack2(wv1.x, wv1.y), pack2(wv1.z, wv1.w) };
#pragma unroll
            for (int i = 0; i < 4; i++)
#pragma unroll
                for (int j = 0; j < 4; j++) fma2(acc[i][j], a2[i], b2[j]);
        }
        __syncthreads();
    }

    if (kt_mode) {
        // stage bias-added results transposed: T[n][m]
#pragma unroll
        for (int i = 0; i < 4; i++) {
            int mm = (ty << 2) + i;
#pragma unroll
            for (int j = 0; j < 4; j++) {
                float2 v = unpack2(acc[i][j]);
                int nn = (tx << 3) + j * 2;
                T[nn][mm]     = v.x + bias[n0 + nn];
                T[nn + 1][mm] = v.y + bias[n0 + nn + 1];
            }
        }
        __syncthreads();
        // coalesced writeout: out[b][n0+row][ml0 + col] rows of 64 floats
        const int bb  = m0 >> 10;
        const int ml0 = m0 & 1023;
#pragma unroll
        for (int r = 0; r < 8; r++) {
            int idx = tid + r * 256;
            int row = idx >> 4;
            int c4  = (idx & 15) << 2;
            float4 v;
            v.x = T[row][c4]; v.y = T[row][c4 + 1];
            v.z = T[row][c4 + 2]; v.w = T[row][c4 + 3];
            *(float4*)&out[((size_t)(bb << 8) + n0 + row) * ML_ + ml0 + c4] = v;
        }
    } else {
#pragma unroll
        for (int i = 0; i < 4; i++) {
            int m = m0 + (ty << 2) + i;
#pragma unroll
            for (int j = 0; j < 4; j++) {
                float2 v = unpack2(acc[i][j]);
                int na = n0 + (tx << 3) + j * 2;
                float2 o = make_float2(v.x + bias[na], v.y + bias[na + 1]);
                *(float2*)&out[(size_t)m * H_ + na] = o;
            }
        }
    }
}

// ---------- K1: fused logits + softmax -> weights ----------
// grid (QL/4, B), 256 threads; thread owns m = 4t..4t+3 for 4 q rows.
#define LQG 4
__global__ __launch_bounds__(256) void logits_softmax_kernel(
    const float* __restrict__ qbuf,    // [B*QL][H]
    const float* __restrict__ kT,      // [B][H][ML]
    const void* __restrict__ mask_raw, // [B][ML]
    const float* __restrict__ wl, const float* __restrict__ blp,
    float* __restrict__ out_w)         // [B*QL][ML]
{
    __shared__ float q_s[LQG][H_];   // 4 KB
    __shared__ float wl_s[H_];       // 1 KB
    __shared__ float red_s[LQG * 8];

    const int t  = threadIdx.x;
    const int b  = blockIdx.y;
    const int q0 = blockIdx.x * LQG;

    for (int i = t; i < LQG * H_; i += 256)
        q_s[i >> 8][i & 255] = qbuf[(size_t)(b * QL_ + q0) * H_ + i];
    wl_s[t] = wl[t];
    __syncthreads();

    const float* kb = kT + (size_t)b * H_ * ML_;
    const int m0 = t * 4;

    float lg[LQG][4];
#pragma unroll
    for (int g = 0; g < LQG; g++)
#pragma unroll
        for (int e = 0; e < 4; e++) lg[g][e] = 0.f;

#pragma unroll 2
    for (int h = 0; h < H_; h++) {
        float4 kv = *(const float4*)&kb[(size_t)h * ML_ + m0];  // coalesced 16B
        float wlh = wl_s[h];
#pragma unroll
        for (int g = 0; g < LQG; g++) {
            float qv = q_s[g][h];
            lg[g][0] = fmaf(wlh, fast_tanh(qv + kv.x), lg[g][0]);
            lg[g][1] = fmaf(wlh, fast_tanh(qv + kv.y), lg[g][1]);
            lg[g][2] = fmaf(wlh, fast_tanh(qv + kv.z), lg[g][2]);
            lg[g][3] = fmaf(wlh, fast_tanh(qv + kv.w), lg[g][3]);
        }
    }

    bool mk[4];
    {
        const int mode = g_mask_mode;
        const int idx = b * ML_ + m0;
        if (mode == 1) {
            const int* mi = (const int*)mask_raw;
#pragma unroll
            for (int e = 0; e < 4; e++) mk[e] = mi[idx + e] != 0;
        } else if (mode == 2) {
            const float* mf = (const float*)mask_raw;
#pragma unroll
            for (int e = 0; e < 4; e++) mk[e] = mf[idx + e] != 0.f;
        } else {
            const unsigned char* mu = (const unsigned char*)mask_raw;
#pragma unroll
            for (int e = 0; e < 4; e++) mk[e] = mu[idx + e] != 0;
        }
    }
    const float blv = *blp;
#pragma unroll
    for (int g = 0; g < LQG; g++)
#pragma unroll
        for (int e = 0; e < 4; e++)
            lg[g][e] = mk[e] ? -1e18f : (lg[g][e] + blv);

    // ---- softmax over m (block covers full ML row), 8 warps ----
    const int lane = t & 31, wid = t >> 5;
    float r[LQG];
#pragma unroll
    for (int g = 0; g < LQG; g++)
        r[g] = fmaxf(fmaxf(lg[g][0], lg[g][1]), fmaxf(lg[g][2], lg[g][3]));
#pragma unroll
    for (int o = 16; o > 0; o >>= 1)
#pragma unroll
        for (int g = 0; g < LQG; g++)
            r[g] = fmaxf(r[g], __shfl_xor_sync(0xffffffffu, r[g], o));
    if (lane == 0) {
#pragma unroll
        for (int g = 0; g < LQG; g++) red_s[g * 8 + wid] = r[g];
    }
    __syncthreads();
    float gmax[LQG];
#pragma unroll
    for (int g = 0; g < LQG; g++) {
        float mx = red_s[g * 8];
#pragma unroll
        for (int j = 1; j < 8; j++) mx = fmaxf(mx, red_s[g * 8 + j]);
        gmax[g] = mx;
    }
    __syncthreads();

#pragma unroll
    for (int g = 0; g < LQG; g++) {
        float s = 0.f;
#pragma unroll
        for (int e = 0; e < 4; e++) {
            lg[g][e] = __expf(lg[g][e] - gmax[g]);
            s += lg[g][e];
        }
        r[g] = s;
    }
#pragma unroll
    for (int o = 16; o > 0; o >>= 1)
#pragma unroll
        for (int g = 0; g < LQG; g++)
            r[g] += __shfl_xor_sync(0xffffffffu, r[g], o);
    if (lane == 0) {
#pragma unroll
        for (int g = 0; g < LQG; g++) red_s[g * 8 + wid] = r[g];
    }
    __syncthreads();
#pragma unroll
    for (int g = 0; g < LQG; g++) {
        float s = red_s[g * 8];
#pragma unroll
        for (int j = 1; j < 8; j++) s += red_s[g * 8 + j];
        float inv = 1.0f / s;
        float4 o;
        o.x = lg[g][0] * inv; o.y = lg[g][1] * inv;
        o.z = lg[g][2] * inv; o.w = lg[g][3] * inv;
        *(float4*)&out_w[(size_t)(b * QL_ + q0 + g) * ML_ + m0] = o;
    }
}

// ---------- K2: AV GEMM with 3-stage cp.async pipeline ----------
#define AM 32
#define AN 64
#define AK 32
#define APAD 36
#define AVSTG 3

__global__ __launch_bounds__(256) void av_gemm_kernel(
    const float* __restrict__ Wt,   // [B][QL][ML]
    const float* __restrict__ Mem,  // [B][ML][KS]
    float* __restrict__ out)        // [B][QL][KS]
{
    __shared__ float As[AVSTG][AM * APAD];
    __shared__ float Bs[AVSTG][AK * AN];

    const int t  = threadIdx.x;
    const int b  = blockIdx.z;
    const int m0 = blockIdx.y * AM;
    const int n0 = blockIdx.x * AN;

    const float* A  = Wt  + (size_t)b * QL_ * ML_;
    const float* Bm = Mem + (size_t)b * ML_ * KS_;

    const int a_row = t >> 3, a_ch = t & 7;
    const int b_row = t >> 4, b_ch = t & 15;

    const int tx = t & 15;   // -> 4 n
    const int ty = t >> 4;   // -> 2 m

    ull acc[2][2] = {{0ull, 0ull}, {0ull, 0ull}};

#define AV_LOAD(buf, k0)                                                        \
    {                                                                           \
        cp_async16(&As[buf][a_row * APAD + a_ch * 4],                           \
                   &A[(size_t)(m0 + a_row) * ML_ + (k0) + a_ch * 4]);           \
        cp_async16(&Bs[buf][b_row * AN + b_ch * 4],                             \
                   &Bm[(size_t)((k0) + b_row) * KS_ + n0 + b_ch * 4]);          \
        cp_async16(&Bs[buf][(b_row + 16) * AN + b_ch * 4],                      \
                   &Bm[(size_t)((k0) + b_row + 16) * KS_ + n0 + b_ch * 4]);     \
        asm volatile("cp.async.commit_group;" ::: "memory");                    \
    }

    AV_LOAD(0, 0)
    AV_LOAD(1, AK)

    const int NIT = ML_ / AK;   // 32
    for (int it = 0; it < NIT; it++) {
        if (it + 2 < NIT) {
            AV_LOAD((it + 2) % AVSTG, (it + 2) * AK)
            asm volatile("cp.async.wait_group 2;" ::: "memory");
        } else if (it + 1 < NIT) {
            asm volatile("cp.async.wait_group 1;" ::: "memory");
        } else {
            asm volatile("cp.async.wait_group 0;" ::: "memory");
        }
        __syncthreads();

        const float* as = As[it % AVSTG];
        const float* bs = Bs[it % AVSTG];
#pragma unroll
        for (int kk = 0; kk < AK; kk++) {
            float a0 = as[(ty * 2)     * APAD + kk];
            float a1 = as[(ty * 2 + 1) * APAD + kk];
            ull b0 = *(const ull*)&bs[kk * AN + tx * 4];
            ull b1 = *(const ull*)&bs[kk * AN + tx * 4 + 2];
            ull A0 = pack2(a0, a0), A1 = pack2(a1, a1);
            fma2(acc[0][0], A0, b0); fma2(acc[0][1], A0, b1);
            fma2(acc[1][0], A1, b0); fma2(acc[1][1], A1, b1);
        }
        __syncthreads();
    }

#pragma unroll
    for (int i = 0; i < 2; i++) {
        float* orow = &out[(size_t)(b * QL_ + m0 + ty * 2 + i) * KS_ + n0 + tx * 4];
        float2 v0 = unpack2(acc[i][0]);
        float2 v1 = unpack2(acc[i][1]);
        *(float2*)&orow[0] = v0;
        *(float2*)&orow[2] = v1;
    }
#undef AV_LOAD
}

// ---------- launch ----------
extern "C" void kernel_launch(void* const* d_in, const int* in_sizes, int n_in,
                              void* d_out, int out_size) {
    const float* query  = (const float*)d_in[0];
    const float* memory = (const float*)d_in[1];
    const void*  mask   = d_in[2];
    const float* Wq = (const float*)d_in[3];
    const float* bq = (const float*)d_in[4];
    const float* Wk = (const float*)d_in[5];
    const float* bk = (const float*)d_in[6];
    const float* wl = (const float*)d_in[7];
    const float* bl = (const float*)d_in[8];

    float* out = (float*)d_out;
    float *qptr, *kptr, *wfb;
    cudaGetSymbolAddress((void**)&qptr, g_q);
    cudaGetSymbolAddress((void**)&kptr, g_kT);
    cudaGetSymbolAddress((void**)&wfb, g_wfallback);

    // output = concat(attns [B,QL,KS], weights [B,QL,ML])
    float* out_attn = out;
    float* out_w = (out_size >= B_ * QL_ * KS_ + B_ * QL_ * ML_)
                       ? (out + B_ * QL_ * KS_) : wfb;

    detect_mask_kernel<<<1, 256>>>((const unsigned char*)mask);
    gemm_bias_kernel<<<dim3(H_ / GBN, (B_ * QL_) / GBM), 256>>>(
        query, Wq, bq, qptr, 512, 0);
    gemm_bias_kernel<<<dim3(H_ / GBN, (B_ * ML_) / GBM), 256>>>(
        memory, Wk, bk, kptr, 512, 1);
    logits_softmax_kernel<<<dim3(QL_ / LQG, B_), 256>>>(
        qptr, kptr, mask, wl, bl, out_w);
    av_gemm_kernel<<<dim3(KS_ / AN, QL_ / AM, B_), 256>>>(
        out_w, memory, out_attn);
}

// round 9
// speedup vs baseline: 1.1059x; 1.1059x over previous
#include <cuda_runtime.h>
#include <cstdint>

// Problem constants
#define B_   8
#define QL_  128
#define ML_  1024
#define KS_  512
#define H_   256

typedef unsigned long long ull;

// ---------- Blackwell packed-f32 helpers ----------
__device__ __forceinline__ ull pack2(float x, float y) {
    ull r; asm("mov.b64 %0, {%1,%2};" : "=l"(r) : "f"(x), "f"(y)); return r;
}
__device__ __forceinline__ void fma2(ull &d, ull a, ull b) {
    asm("fma.rn.f32x2 %0, %1, %2, %0;" : "+l"(d) : "l"(a), "l"(b));
}
__device__ __forceinline__ float2 unpack2(ull v) {
    float2 f; asm("mov.b64 {%0,%1}, %2;" : "=f"(f.x), "=f"(f.y) : "l"(v)); return f;
}
__device__ __forceinline__ float fast_tanh(float x) {
    float r; asm("tanh.approx.f32 %0, %1;" : "=f"(r) : "f"(x)); return r;
}

// ---------- scratch ----------
__device__ float g_q[B_ * QL_ * H_];          // [B*QL][H]
__device__ float g_kT[B_ * H_ * ML_];         // [B][H][ML]
__device__ float g_wfallback[B_ * QL_ * ML_];
__device__ int   g_mask_mode;                 // 0=u8, 1=i32, 2=f32

// ---------- mask dtype auto-detection ----------
__global__ void detect_mask_kernel(const unsigned char* __restrict__ m) {
    __shared__ int viol[3];
    if (threadIdx.x < 3) viol[threadIdx.x] = 0;
    __syncthreads();
    int v_u8 = 0, v_i32 = 0, v_f32 = 0;
    for (int i = threadIdx.x; i < B_ * ML_; i += 256) {
        unsigned char b = m[i];
        int r = i & 3;
        if (b > 1) v_u8++;
        if (r != 0 && b != 0) v_i32++;
        if (r == 0 || r == 1) { if (b != 0) v_f32++; }
        else if (r == 2)      { if (b != 0 && b != 128) v_f32++; }
        else                  { if (b != 0 && b != 63)  v_f32++; }
    }
    atomicAdd(&viol[0], v_u8);
    atomicAdd(&viol[1], v_i32);
    atomicAdd(&viol[2], v_f32);
    __syncthreads();
    if (threadIdx.x == 0) {
        int mode;
        if      (viol[1] == 0) mode = 1;
        else if (viol[2] == 0) mode = 2;
        else                   mode = 0;
        g_mask_mode = mode;
    }
}

// ---------- projection GEMM (register double-buffered, from R7) ----------
#define GBM 64
#define GBN 128
#define GBK 16

__global__ __launch_bounds__(256) void gemm_bias_kernel(
    const float* __restrict__ A, const float* __restrict__ W,
    const float* __restrict__ bias, float* __restrict__ out,
    int K, int kt_mode)
{
    __shared__ float As[GBK][GBM];
    __shared__ float Ws[GBK][GBN];
    __shared__ float T[GBN][GBM + 1];

    const int tid = threadIdx.x;
    const int tx = tid & 15;
    const int ty = tid >> 4;
    const int m0 = blockIdx.y * GBM;
    const int n0 = blockIdx.x * GBN;

    ull acc[4][4];
#pragma unroll
    for (int i = 0; i < 4; i++)
#pragma unroll
        for (int j = 0; j < 4; j++) acc[i][j] = 0ull;

    const int arow = tid >> 2;
    const int acol = (tid & 3) << 2;

    float4 av = *(const float4*)&A[(size_t)(m0 + arow) * K + acol];
    float4 w0 = *(const float4*)&W[(size_t)(n0 + arow) * K + acol];
    float4 w1 = *(const float4*)&W[(size_t)(n0 + arow + 64) * K + acol];

    for (int k0 = 0; k0 < K; k0 += GBK) {
        As[acol + 0][arow] = av.x; As[acol + 1][arow] = av.y;
        As[acol + 2][arow] = av.z; As[acol + 3][arow] = av.w;
        Ws[acol + 0][arow] = w0.x; Ws[acol + 1][arow] = w0.y;
        Ws[acol + 2][arow] = w0.z; Ws[acol + 3][arow] = w0.w;
        Ws[acol + 0][arow + 64] = w1.x; Ws[acol + 1][arow + 64] = w1.y;
        Ws[acol + 2][arow + 64] = w1.z; Ws[acol + 3][arow + 64] = w1.w;
        __syncthreads();

        if (k0 + GBK < K) {
            av = *(const float4*)&A[(size_t)(m0 + arow) * K + k0 + GBK + acol];
            w0 = *(const float4*)&W[(size_t)(n0 + arow) * K + k0 + GBK + acol];
            w1 = *(const float4*)&W[(size_t)(n0 + arow + 64) * K + k0 + GBK + acol];
        }

#pragma unroll
        for (int kk = 0; kk < GBK; kk++) {
            float4 a4  = *(const float4*)&As[kk][ty << 2];
            float4 wv0 = *(const float4*)&Ws[kk][tx << 3];
            float4 wv1 = *(const float4*)&Ws[kk][(tx << 3) + 4];
            ull a2[4] = { pack2(a4.x, a4.x), pack2(a4.y, a4.y),
                          pack2(a4.z, a4.z), pack2(a4.w, a4.w) };
            ull b2[4] = { pack2(wv0.x, wv0.y), pack2(wv0.z, wv0.w),
                          pack2(wv1.x, wv1.y), pack2(wv1.z, wv1.w) };
#pragma unroll
            for (int i = 0; i < 4; i++)
#pragma unroll
                for (int j = 0; j < 4; j++) fma2(acc[i][j], a2[i], b2[j]);
        }
        __syncthreads();
    }

    if (kt_mode) {
#pragma unroll
        for (int i = 0; i < 4; i++) {
            int mm = (ty << 2) + i;
#pragma unroll
            for (int j = 0; j < 4; j++) {
                float2 v = unpack2(acc[i][j]);
                int nn = (tx << 3) + j * 2;
                T[nn][mm]     = v.x + bias[n0 + nn];
                T[nn + 1][mm] = v.y + bias[n0 + nn + 1];
            }
        }
        __syncthreads();
        const int bb  = m0 >> 10;
        const int ml0 = m0 & 1023;
#pragma unroll
        for (int r = 0; r < 8; r++) {
            int idx = tid + r * 256;
            int row = idx >> 4;
            int c4  = (idx & 15) << 2;
            float4 v;
            v.x = T[row][c4]; v.y = T[row][c4 + 1];
            v.z = T[row][c4 + 2]; v.w = T[row][c4 + 3];
            *(float4*)&out[((size_t)(bb << 8) + n0 + row) * ML_ + ml0 + c4] = v;
        }
    } else {
#pragma unroll
        for (int i = 0; i < 4; i++) {
            int m = m0 + (ty << 2) + i;
#pragma unroll
            for (int j = 0; j < 4; j++) {
                float2 v = unpack2(acc[i][j]);
                int na = n0 + (tx << 3) + j * 2;
                float2 o = make_float2(v.x + bias[na], v.y + bias[na + 1]);
                *(float2*)&out[(size_t)m * H_ + na] = o;
            }
        }
    }
}

// ---------- K1: fused logits + softmax + AV ----------
// grid (QL/4, B), 512 threads.
// Phase B: thread owns m = 2t, 2t+1 for 4 q rows (round-6 MUFU-saturating shape).
// Phase C: thread owns output column t of KS for the same 4 q rows.
#define LQG 4
__global__ __launch_bounds__(512) void attn_fused_kernel(
    const float* __restrict__ qbuf,    // [B*QL][H]
    const float* __restrict__ kT,      // [B][H][ML]
    const float* __restrict__ memory,  // [B][ML][KS]
    const void* __restrict__ mask_raw, // [B][ML]
    const float* __restrict__ wl, const float* __restrict__ blp,
    float* __restrict__ out_attn,      // [B][QL][KS]
    float* __restrict__ out_w)         // [B*QL][ML]
{
    __shared__ float q_s[LQG][H_];                    // 4 KB
    __shared__ float wl_s[H_];                        // 1 KB
    __shared__ __align__(16) float w_s[ML_][LQG];     // 16 KB
    __shared__ float red_s[LQG * 16];

    const int t  = threadIdx.x;
    const int b  = blockIdx.y;
    const int q0 = blockIdx.x * LQG;

    for (int i = t; i < LQG * H_; i += 512)
        q_s[i >> 8][i & 255] = qbuf[(size_t)(b * QL_ + q0) * H_ + i];
    if (t < H_) wl_s[t] = wl[t];
    __syncthreads();

    const float* kb = kT + (size_t)b * H_ * ML_;
    const int m0 = t * 2;

    // ---- phase B: logits ----
    float lg[LQG][2];
#pragma unroll
    for (int g = 0; g < LQG; g++) { lg[g][0] = 0.f; lg[g][1] = 0.f; }

#pragma unroll 4
    for (int h = 0; h < H_; h++) {
        float2 kv = *(const float2*)&kb[(size_t)h * ML_ + m0];
        float wlh = wl_s[h];
#pragma unroll
        for (int g = 0; g < LQG; g++) {
            float qv = q_s[g][h];
            lg[g][0] = fmaf(wlh, fast_tanh(qv + kv.x), lg[g][0]);
            lg[g][1] = fmaf(wlh, fast_tanh(qv + kv.y), lg[g][1]);
        }
    }

    bool mk0, mk1;
    {
        const int mode = g_mask_mode;
        const int idx = b * ML_ + m0;
        if (mode == 1) {
            const int* mi = (const int*)mask_raw;
            mk0 = mi[idx] != 0; mk1 = mi[idx + 1] != 0;
        } else if (mode == 2) {
            const float* mf = (const float*)mask_raw;
            mk0 = mf[idx] != 0.f; mk1 = mf[idx + 1] != 0.f;
        } else {
            const unsigned char* mu = (const unsigned char*)mask_raw;
            mk0 = mu[idx] != 0; mk1 = mu[idx + 1] != 0;
        }
    }
    const float blv = *blp;
#pragma unroll
    for (int g = 0; g < LQG; g++) {
        lg[g][0] = mk0 ? -1e18f : (lg[g][0] + blv);
        lg[g][1] = mk1 ? -1e18f : (lg[g][1] + blv);
    }

    // ---- softmax over m (block covers the full ML row), 16 warps ----
    const int lane = t & 31, wid = t >> 5;
    float r[LQG];
#pragma unroll
    for (int g = 0; g < LQG; g++) r[g] = fmaxf(lg[g][0], lg[g][1]);
#pragma unroll
    for (int o = 16; o > 0; o >>= 1)
#pragma unroll
        for (int g = 0; g < LQG; g++)
            r[g] = fmaxf(r[g], __shfl_xor_sync(0xffffffffu, r[g], o));
    if (lane == 0) {
#pragma unroll
        for (int g = 0; g < LQG; g++) red_s[g * 16 + wid] = r[g];
    }
    __syncthreads();
    float gmax[LQG];
#pragma unroll
    for (int g = 0; g < LQG; g++) {
        float mx = red_s[g * 16];
#pragma unroll
        for (int j = 1; j < 16; j++) mx = fmaxf(mx, red_s[g * 16 + j]);
        gmax[g] = mx;
    }
    __syncthreads();

    float e0[LQG], e1[LQG];
#pragma unroll
    for (int g = 0; g < LQG; g++) {
        e0[g] = __expf(lg[g][0] - gmax[g]);
        e1[g] = __expf(lg[g][1] - gmax[g]);
        r[g]  = e0[g] + e1[g];
    }
#pragma unroll
    for (int o = 16; o > 0; o >>= 1)
#pragma unroll
        for (int g = 0; g < LQG; g++)
            r[g] += __shfl_xor_sync(0xffffffffu, r[g], o);
    if (lane == 0) {
#pragma unroll
        for (int g = 0; g < LQG; g++) red_s[g * 16 + wid] = r[g];
    }
    __syncthreads();
#pragma unroll
    for (int g = 0; g < LQG; g++) {
        float s = red_s[g * 16];
#pragma unroll
        for (int j = 1; j < 16; j++) s += red_s[g * 16 + j];
        float inv = 1.0f / s;
        float w0v = e0[g] * inv;
        float w1v = e1[g] * inv;
        w_s[m0][g]     = w0v;
        w_s[m0 + 1][g] = w1v;
        *(float2*)&out_w[(size_t)(b * QL_ + q0 + g) * ML_ + m0] = make_float2(w0v, w1v);
    }
    __syncthreads();

    // ---- phase C: attns = weights @ memory (thread = KS column t) ----
    const float* memb = memory + (size_t)b * ML_ * KS_ + t;
    ull acc2[2] = {0ull, 0ull};   // g pairs (0,1) and (2,3)
#pragma unroll 8
    for (int m = 0; m < ML_; m++) {
        float mv = memb[(size_t)m * KS_];        // coalesced across warp
        ull mv2 = pack2(mv, mv);
        ull wp0 = *(const ull*)&w_s[m][0];       // broadcast LDS.64
        ull wp1 = *(const ull*)&w_s[m][2];
        fma2(acc2[0], wp0, mv2);
        fma2(acc2[1], wp1, mv2);
    }
    {
        float2 v0 = unpack2(acc2[0]);
        float2 v1 = unpack2(acc2[1]);
        out_attn[(size_t)(b * QL_ + q0 + 0) * KS_ + t] = v0.x;
        out_attn[(size_t)(b * QL_ + q0 + 1) * KS_ + t] = v0.y;
        out_attn[(size_t)(b * QL_ + q0 + 2) * KS_ + t] = v1.x;
        out_attn[(size_t)(b * QL_ + q0 + 3) * KS_ + t] = v1.y;
    }
}

// ---------- launch ----------
extern "C" void kernel_launch(void* const* d_in, const int* in_sizes, int n_in,
                              void* d_out, int out_size) {
    const float* query  = (const float*)d_in[0];
    const float* memory = (const float*)d_in[1];
    const void*  mask   = d_in[2];
    const float* Wq = (const float*)d_in[3];
    const float* bq = (const float*)d_in[4];
    const float* Wk = (const float*)d_in[5];
    const float* bk = (const float*)d_in[6];
    const float* wl = (const float*)d_in[7];
    const float* bl = (const float*)d_in[8];

    float* out = (float*)d_out;
    float *qptr, *kptr, *wfb;
    cudaGetSymbolAddress((void**)&qptr, g_q);
    cudaGetSymbolAddress((void**)&kptr, g_kT);
    cudaGetSymbolAddress((void**)&wfb, g_wfallback);

    // output = concat(attns [B,QL,KS], weights [B,QL,ML])
    float* out_attn = out;
    float* out_w = (out_size >= B_ * QL_ * KS_ + B_ * QL_ * ML_)
                       ? (out + B_ * QL_ * KS_) : wfb;

    detect_mask_kernel<<<1, 256>>>((const unsigned char*)mask);
    gemm_bias_kernel<<<dim3(H_ / GBN, (B_ * QL_) / GBM), 256>>>(
        query, Wq, bq, qptr, 512, 0);
    gemm_bias_kernel<<<dim3(H_ / GBN, (B_ * ML_) / GBM), 256>>>(
        memory, Wk, bk, kptr, 512, 1);
    attn_fused_kernel<<<dim3(QL_ / LQG, B_), 512>>>(
        qptr, kptr, memory, mask, wl, bl, out_attn, out_w);
}

// round 11
// speedup vs baseline: 1.1451x; 1.0354x over previous
#include <cuda_runtime.h>
#include <cstdint>

// Problem constants
#define B_   8
#define QL_  128
#define ML_  1024
#define KS_  512
#define H_   256

typedef unsigned long long ull;

// ---------- Blackwell packed-f32 helpers ----------
__device__ __forceinline__ ull pack2(float x, float y) {
    ull r; asm("mov.b64 %0, {%1,%2};" : "=l"(r) : "f"(x), "f"(y)); return r;
}
__device__ __forceinline__ void fma2(ull &d, ull a, ull b) {
    asm("fma.rn.f32x2 %0, %1, %2, %0;" : "+l"(d) : "l"(a), "l"(b));
}
__device__ __forceinline__ float2 unpack2(ull v) {
    float2 f; asm("mov.b64 {%0,%1}, %2;" : "=f"(f.x), "=f"(f.y) : "l"(v)); return f;
}
__device__ __forceinline__ float fast_tanh(float x) {
    float r; asm("tanh.approx.f32 %0, %1;" : "=f"(r) : "f"(x)); return r;
}

// XOR swizzle for conflict-free GEMM smem staging (bits >=3 only)
#define SWZ(r) (((r) & 12) << 1)

// ---------- scratch ----------
__device__ float g_q[B_ * QL_ * H_];          // [B*QL][H]
__device__ float g_kT[B_ * H_ * ML_];         // [B][H][ML]
__device__ float g_wfallback[B_ * QL_ * ML_];
__device__ int   g_mask_mode;                 // 0=u8, 1=i32, 2=f32

// ---------- mask dtype auto-detection ----------
__global__ void detect_mask_kernel(const unsigned char* __restrict__ m) {
    __shared__ int viol[3];
    if (threadIdx.x < 3) viol[threadIdx.x] = 0;
    __syncthreads();
    int v_u8 = 0, v_i32 = 0, v_f32 = 0;
    for (int i = threadIdx.x; i < B_ * ML_; i += 256) {
        unsigned char b = m[i];
        int r = i & 3;
        if (b > 1) v_u8++;
        if (r != 0 && b != 0) v_i32++;
        if (r == 0 || r == 1) { if (b != 0) v_f32++; }
        else if (r == 2)      { if (b != 0 && b != 128) v_f32++; }
        else                  { if (b != 0 && b != 63)  v_f32++; }
    }
    atomicAdd(&viol[0], v_u8);
    atomicAdd(&viol[1], v_i32);
    atomicAdd(&viol[2], v_f32);
    __syncthreads();
    if (threadIdx.x == 0) {
        int mode;
        if      (viol[1] == 0) mode = 1;
        else if (viol[2] == 0) mode = 2;
        else                   mode = 0;
        g_mask_mode = mode;
    }
}

// ---------- projection GEMM (reg double-buffered, swizzled smem) ----------
#define GBM 64
#define GBN 128
#define GBK 16

__global__ __launch_bounds__(256) void gemm_bias_kernel(
    const float* __restrict__ A, const float* __restrict__ W,
    const float* __restrict__ bias, float* __restrict__ out,
    int K, int kt_mode)
{
    __shared__ float As[GBK][GBM];
    __shared__ float Ws[GBK][GBN];
    __shared__ float T[GBN][GBM + 1];

    const int tid = threadIdx.x;
    const int tx = tid & 15;
    const int ty = tid >> 4;
    const int m0 = blockIdx.y * GBM;
    const int n0 = blockIdx.x * GBN;

    ull acc[4][4];
#pragma unroll
    for (int i = 0; i < 4; i++)
#pragma unroll
        for (int j = 0; j < 4; j++) acc[i][j] = 0ull;

    const int arow = tid >> 2;
    const int acol = (tid & 3) << 2;
    const int sws  = SWZ(acol);          // staging swizzle (same for i=0..3)
    const int arow_s  = arow ^ sws;
    const int arow64_s = (arow + 64) ^ sws;

    float4 av = *(const float4*)&A[(size_t)(m0 + arow) * K + acol];
    float4 w0 = *(const float4*)&W[(size_t)(n0 + arow) * K + acol];
    float4 w1 = *(const float4*)&W[(size_t)(n0 + arow + 64) * K + acol];

    for (int k0 = 0; k0 < K; k0 += GBK) {
        As[acol + 0][arow_s] = av.x; As[acol + 1][arow_s] = av.y;
        As[acol + 2][arow_s] = av.z; As[acol + 3][arow_s] = av.w;
        Ws[acol + 0][arow_s] = w0.x; Ws[acol + 1][arow_s] = w0.y;
        Ws[acol + 2][arow_s] = w0.z; Ws[acol + 3][arow_s] = w0.w;
        Ws[acol + 0][arow64_s] = w1.x; Ws[acol + 1][arow64_s] = w1.y;
        Ws[acol + 2][arow64_s] = w1.z; Ws[acol + 3][arow64_s] = w1.w;
        __syncthreads();

        if (k0 + GBK < K) {
            av = *(const float4*)&A[(size_t)(m0 + arow) * K + k0 + GBK + acol];
            w0 = *(const float4*)&W[(size_t)(n0 + arow) * K + k0 + GBK + acol];
            w1 = *(const float4*)&W[(size_t)(n0 + arow + 64) * K + k0 + GBK + acol];
        }

#pragma unroll
        for (int kk = 0; kk < GBK; kk++) {
            const int swk = SWZ(kk);
            float4 a4 = *(const float4*)&As[kk][(ty << 2) ^ swk];
            const int bcol = (tx << 3) ^ swk;
            ulonglong2 bv0 = *(const ulonglong2*)&Ws[kk][bcol];
            ulonglong2 bv1 = *(const ulonglong2*)&Ws[kk][bcol + 4];
            ull a2[4] = { pack2(a4.x, a4.x), pack2(a4.y, a4.y),
                          pack2(a4.z, a4.z), pack2(a4.w, a4.w) };
            ull b2[4] = { bv0.x, bv0.y, bv1.x, bv1.y };
#pragma unroll
            for (int i = 0; i < 4; i++)
#pragma unroll
                for (int j = 0; j < 4; j++) fma2(acc[i][j], a2[i], b2[j]);
        }
        __syncthreads();
    }

    if (kt_mode) {
#pragma unroll
        for (int i = 0; i < 4; i++) {
            int mm = (ty << 2) + i;
#pragma unroll
            for (int j = 0; j < 4; j++) {
                float2 v = unpack2(acc[i][j]);
                int nn = (tx << 3) + j * 2;
                T[nn][mm]     = v.x + bias[n0 + nn];
                T[nn + 1][mm] = v.y + bias[n0 + nn + 1];
            }
        }
        __syncthreads();
        const int bb  = m0 >> 10;
        const int ml0 = m0 & 1023;
#pragma unroll
        for (int r = 0; r < 8; r++) {
            int idx = tid + r * 256;
            int row = idx >> 4;
            int c4  = (idx & 15) << 2;
            float4 v;
            v.x = T[row][c4]; v.y = T[row][c4 + 1];
            v.z = T[row][c4 + 2]; v.w = T[row][c4 + 3];
            *(float4*)&out[((size_t)(bb << 8) + n0 + row) * ML_ + ml0 + c4] = v;
        }
    } else {
#pragma unroll
        for (int i = 0; i < 4; i++) {
            int m = m0 + (ty << 2) + i;
#pragma unroll
            for (int j = 0; j < 4; j++) {
                float2 v = unpack2(acc[i][j]);
                int na = n0 + (tx << 3) + j * 2;
                float2 o = make_float2(v.x + bias[na], v.y + bias[na + 1]);
                *(float2*)&out[(size_t)m * H_ + na] = o;
            }
        }
    }
}

// ---------- K1: fused logits + softmax + AV ----------
// grid (QL/4, B), 512 threads.
// Phase B: thread owns m = 2t, 2t+1 for 4 q rows.
// Phase C: thread owns KS cols (2c, 2c+1), m-half mh; cross-half smem combine.
#define LQG 4
__global__ __launch_bounds__(512) void attn_fused_kernel(
    const float* __restrict__ qbuf,    // [B*QL][H]
    const float* __restrict__ kT,      // [B][H][ML]
    const float* __restrict__ memory,  // [B][ML][KS]
    const void* __restrict__ mask_raw, // [B][ML]
    const float* __restrict__ wl, const float* __restrict__ blp,
    float* __restrict__ out_attn,      // [B][QL][KS]
    float* __restrict__ out_w)         // [B*QL][ML]
{
    __shared__ float q_s[LQG][H_];                    // 4 KB
    __shared__ float wl_s[H_];                        // 1 KB
    __shared__ __align__(16) float w_s[ML_][LQG];     // 16 KB (aliased by ps later)
    __shared__ float red_s[LQG * 16];

    const int t  = threadIdx.x;
    const int b  = blockIdx.y;
    const int q0 = blockIdx.x * LQG;

    for (int i = t; i < LQG * H_; i += 512)
        q_s[i >> 8][i & 255] = qbuf[(size_t)(b * QL_ + q0) * H_ + i];
    if (t < H_) wl_s[t] = wl[t];
    __syncthreads();

    const float* kb = kT + (size_t)b * H_ * ML_;
    const int m0 = t * 2;

    // ---- phase B: logits (MUFU.TANH-bound) ----
    float lg[LQG][2];
#pragma unroll
    for (int g = 0; g < LQG; g++) { lg[g][0] = 0.f; lg[g][1] = 0.f; }

#pragma unroll 4
    for (int h = 0; h < H_; h++) {
        float2 kv = *(const float2*)&kb[(size_t)h * ML_ + m0];
        float wlh = wl_s[h];
#pragma unroll
        for (int g = 0; g < LQG; g++) {
            float qv = q_s[g][h];
            lg[g][0] = fmaf(wlh, fast_tanh(qv + kv.x), lg[g][0]);
            lg[g][1] = fmaf(wlh, fast_tanh(qv + kv.y), lg[g][1]);
        }
    }

    bool mk0, mk1;
    {
        const int mode = g_mask_mode;
        const int idx = b * ML_ + m0;
        if (mode == 1) {
            const int* mi = (const int*)mask_raw;
            mk0 = mi[idx] != 0; mk1 = mi[idx + 1] != 0;
        } else if (mode == 2) {
            const float* mf = (const float*)mask_raw;
            mk0 = mf[idx] != 0.f; mk1 = mf[idx + 1] != 0.f;
        } else {
            const unsigned char* mu = (const unsigned char*)mask_raw;
            mk0 = mu[idx] != 0; mk1 = mu[idx + 1] != 0;
        }
    }
    const float blv = *blp;
#pragma unroll
    for (int g = 0; g < LQG; g++) {
        lg[g][0] = mk0 ? -1e18f : (lg[g][0] + blv);
        lg[g][1] = mk1 ? -1e18f : (lg[g][1] + blv);
    }

    // ---- softmax (16 warps, full ML row in block) ----
    const int lane = t & 31, wid = t >> 5;
    float r[LQG];
#pragma unroll
    for (int g = 0; g < LQG; g++) r[g] = fmaxf(lg[g][0], lg[g][1]);
#pragma unroll
    for (int o = 16; o > 0; o >>= 1)
#pragma unroll
        for (int g = 0; g < LQG; g++)
            r[g] = fmaxf(r[g], __shfl_xor_sync(0xffffffffu, r[g], o));
    if (lane == 0) {
#pragma unroll
        for (int g = 0; g < LQG; g++) red_s[g * 16 + wid] = r[g];
    }
    __syncthreads();
    float gmax[LQG];
#pragma unroll
    for (int g = 0; g < LQG; g++) {
        float mx = red_s[g * 16];
#pragma unroll
        for (int j = 1; j < 16; j++) mx = fmaxf(mx, red_s[g * 16 + j]);
        gmax[g] = mx;
    }
    __syncthreads();

    float e0[LQG], e1[LQG];
#pragma unroll
    for (int g = 0; g < LQG; g++) {
        e0[g] = __expf(lg[g][0] - gmax[g]);
        e1[g] = __expf(lg[g][1] - gmax[g]);
        r[g]  = e0[g] + e1[g];
    }
#pragma unroll
    for (int o = 16; o > 0; o >>= 1)
#pragma unroll
        for (int g = 0; g < LQG; g++)
            r[g] += __shfl_xor_sync(0xffffffffu, r[g], o);
    if (lane == 0) {
#pragma unroll
        for (int g = 0; g < LQG; g++) red_s[g * 16 + wid] = r[g];
    }
    __syncthreads();
#pragma unroll
    for (int g = 0; g < LQG; g++) {
        float s = red_s[g * 16];
#pragma unroll
        for (int j = 1; j < 16; j++) s += red_s[g * 16 + j];
        float inv = 1.0f / s;
        float w0v = e0[g] * inv;
        float w1v = e1[g] * inv;
        w_s[m0][g]     = w0v;
        w_s[m0 + 1][g] = w1v;
        *(float2*)&out_w[(size_t)(b * QL_ + q0 + g) * ML_ + m0] = make_float2(w0v, w1v);
    }
    __syncthreads();

    // ---- phase C: attns = weights @ memory ----
    // thread: cols (2c, 2c+1), m-half mh (512 m each); LDG.64 per iter.
    const int mh = t >> 8;        // 0 / 1
    const int c  = t & 255;
    const float* memb = memory + (size_t)b * ML_ * KS_
                        + (size_t)mh * 512 * KS_ + 2 * c;
    ull acc2[LQG] = {0ull, 0ull, 0ull, 0ull};
#pragma unroll 8
    for (int m = 0; m < 512; m++) {
        ull mv2 = *(const ull*)&memb[(size_t)m * KS_];          // 2 cols, coalesced
        float4 wv = *(const float4*)&w_s[mh * 512 + m][0];      // broadcast LDS.128
        fma2(acc2[0], pack2(wv.x, wv.x), mv2);
        fma2(acc2[1], pack2(wv.y, wv.y), mv2);
        fma2(acc2[2], pack2(wv.z, wv.z), mv2);
        fma2(acc2[3], pack2(wv.w, wv.w), mv2);
    }

    // combine halves: mh=1 publishes partials via smem (alias w_s), mh=0 sums+stores
    __syncthreads();                       // everyone done reading w_s
    float* ps = &w_s[0][0];                // 256 x 9 floats, conflict-free stride
    if (mh == 1) {
#pragma unroll
        for (int g = 0; g < LQG; g++) {
            float2 v = unpack2(acc2[g]);
            ps[c * 9 + g * 2]     = v.x;
            ps[c * 9 + g * 2 + 1] = v.y;
        }
    }
    __syncthreads();
    if (mh == 0) {
#pragma unroll
        for (int g = 0; g < LQG; g++) {
            float2 v = unpack2(acc2[g]);
            v.x += ps[c * 9 + g * 2];
            v.y += ps[c * 9 + g * 2 + 1];
            *(float2*)&out_attn[(size_t)(b * QL_ + q0 + g) * KS_ + 2 * c] = v;
        }
    }
}

// ---------- launch ----------
extern "C" void kernel_launch(void* const* d_in, const int* in_sizes, int n_in,
                              void* d_out, int out_size) {
    const float* query  = (const float*)d_in[0];
    const float* memory = (const float*)d_in[1];
    const void*  mask   = d_in[2];
    const float* Wq = (const float*)d_in[3];
    const float* bq = (const float*)d_in[4];
    const float* Wk = (const float*)d_in[5];
    const float* bk = (const float*)d_in[6];
    const float* wl = (const float*)d_in[7];
    const float* bl = (const float*)d_in[8];

    float* out = (float*)d_out;
    float *qptr, *kptr, *wfb;
    cudaGetSymbolAddress((void**)&qptr, g_q);
    cudaGetSymbolAddress((void**)&kptr, g_kT);
    cudaGetSymbolAddress((void**)&wfb, g_wfallback);

    // output = concat(attns [B,QL,KS], weights [B,QL,ML])
    float* out_attn = out;
    float* out_w = (out_size >= B_ * QL_ * KS_ + B_ * QL_ * ML_)
                       ? (out + B_ * QL_ * KS_) : wfb;

    detect_mask_kernel<<<1, 256>>>((const unsigned char*)mask);
    gemm_bias_kernel<<<dim3(H_ / GBN, (B_ * QL_) / GBM), 256>>>(
        query, Wq, bq, qptr, 512, 0);
    gemm_bias_kernel<<<dim3(H_ / GBN, (B_ * ML_) / GBM), 256>>>(
        memory, Wk, bk, kptr, 512, 1);
    attn_fused_kernel<<<dim3(QL_ / LQG, B_), 512>>>(
        qptr, kptr, memory, mask, wl, bl, out_attn, out_w);
}

// round 14
// speedup vs baseline: 1.2935x; 1.1296x over previous
#include <cuda_runtime.h>
#include <cstdint>

// Problem constants
#define B_   8
#define QL_  128
#define ML_  1024
#define KS_  512
#define H_   256

typedef unsigned long long ull;

// ---------- Blackwell packed-f32 helpers ----------
__device__ __forceinline__ ull pack2(float x, float y) {
    ull r; asm("mov.b64 %0, {%1,%2};" : "=l"(r) : "f"(x), "f"(y)); return r;
}
__device__ __forceinline__ void fma2(ull &d, ull a, ull b) {
    asm("fma.rn.f32x2 %0, %1, %2, %0;" : "+l"(d) : "l"(a), "l"(b));
}
__device__ __forceinline__ float2 unpack2(ull v) {
    float2 f; asm("mov.b64 {%0,%1}, %2;" : "=f"(f.x), "=f"(f.y) : "l"(v)); return f;
}
__device__ __forceinline__ float fast_tanh(float x) {
    float r; asm("tanh.approx.f32 %0, %1;" : "=f"(r) : "f"(x)); return r;
}

// XOR swizzle for conflict-free GEMM smem staging (bits >=3 only)
#define SWZ(r) (((r) & 12) << 1)

// ---------- scratch ----------
__device__ float g_q[B_ * QL_ * H_];          // [B*QL][H]
__device__ float g_kT[B_ * H_ * ML_];         // [B][H][ML]
__device__ float g_wfallback[B_ * QL_ * ML_];
__device__ int   g_mask_mode;                 // 0=u8, 1=i32, 2=f32

// ---------- merged kernel: mask-detect (block 0) + q-proj + k-proj ----------
// grid: 1 + 2*(16 + 128) = 289 blocks, 256 threads.
// tile = bid-1; nt = tile&1 (n0 = nt*128); mt = tile>>1:
//   mt < 16  -> q projection rows [mt*64, +64)    (out row-major [M][H])
//   mt >= 16 -> k projection rows [(mt-16)*64,+64) (out transposed [b][n][ml])
#define GBM 64
#define GBN 128
#define GBK 16

__global__ __launch_bounds__(256) void proj_kernel(
    const float* __restrict__ query, const float* __restrict__ Wq,
    const float* __restrict__ bq, float* __restrict__ qout,
    const float* __restrict__ memory, const float* __restrict__ Wk,
    const float* __restrict__ bk, float* __restrict__ kout,
    const unsigned char* __restrict__ mask_bytes)
{
    const int bid = blockIdx.x;
    const int tid = threadIdx.x;

    if (bid == 0) {
        // ---- mask dtype auto-detection ----
        __shared__ int viol[3];
        if (tid < 3) viol[tid] = 0;
        __syncthreads();
        int v_u8 = 0, v_i32 = 0, v_f32 = 0;
        for (int i = tid; i < B_ * ML_; i += 256) {
            unsigned char b = mask_bytes[i];
            int r = i & 3;
            if (b > 1) v_u8++;
            if (r != 0 && b != 0) v_i32++;
            if (r == 0 || r == 1) { if (b != 0) v_f32++; }
            else if (r == 2)      { if (b != 0 && b != 128) v_f32++; }
            else                  { if (b != 0 && b != 63)  v_f32++; }
        }
        atomicAdd(&viol[0], v_u8);
        atomicAdd(&viol[1], v_i32);
        atomicAdd(&viol[2], v_f32);
        __syncthreads();
        if (tid == 0) {
            int mode;
            if      (viol[1] == 0) mode = 1;
            else if (viol[2] == 0) mode = 2;
            else                   mode = 0;
            g_mask_mode = mode;
        }
        return;
    }

    __shared__ float As[GBK][GBM];
    __shared__ float Ws[GBK][GBN];
    __shared__ float T[GBN][GBM + 1];

    const int tile = bid - 1;
    const int nt = tile & 1;
    const int mt = tile >> 1;
    const int kt_mode = (mt >= 16);
    const float* A    = kt_mode ? memory : query;
    const float* W    = kt_mode ? Wk : Wq;
    const float* bias = kt_mode ? bk : bq;
    float* out        = kt_mode ? kout : qout;
    const int m0 = (kt_mode ? (mt - 16) : mt) * GBM;
    const int n0 = nt * GBN;
    const int K = 512;

    const int tx = tid & 15;
    const int ty = tid >> 4;

    ull acc[4][4];
#pragma unroll
    for (int i = 0; i < 4; i++)
#pragma unroll
        for (int j = 0; j < 4; j++) acc[i][j] = 0ull;

    const int arow = tid >> 2;
    const int acol = (tid & 3) << 2;
    const int sws  = SWZ(acol);
    const int arow_s   = arow ^ sws;
    const int arow64_s = (arow + 64) ^ sws;

    float4 av = *(const float4*)&A[(size_t)(m0 + arow) * K + acol];
    float4 w0 = *(const float4*)&W[(size_t)(n0 + arow) * K + acol];
    float4 w1 = *(const float4*)&W[(size_t)(n0 + arow + 64) * K + acol];

    for (int k0 = 0; k0 < K; k0 += GBK) {
        As[acol + 0][arow_s] = av.x; As[acol + 1][arow_s] = av.y;
        As[acol + 2][arow_s] = av.z; As[acol + 3][arow_s] = av.w;
        Ws[acol + 0][arow_s] = w0.x; Ws[acol + 1][arow_s] = w0.y;
        Ws[acol + 2][arow_s] = w0.z; Ws[acol + 3][arow_s] = w0.w;
        Ws[acol + 0][arow64_s] = w1.x; Ws[acol + 1][arow64_s] = w1.y;
        Ws[acol + 2][arow64_s] = w1.z; Ws[acol + 3][arow64_s] = w1.w;
        __syncthreads();

        if (k0 + GBK < K) {
            av = *(const float4*)&A[(size_t)(m0 + arow) * K + k0 + GBK + acol];
            w0 = *(const float4*)&W[(size_t)(n0 + arow) * K + k0 + GBK + acol];
            w1 = *(const float4*)&W[(size_t)(n0 + arow + 64) * K + k0 + GBK + acol];
        }

#pragma unroll
        for (int kk = 0; kk < GBK; kk++) {
            const int swk = SWZ(kk);
            float4 a4 = *(const float4*)&As[kk][(ty << 2) ^ swk];
            const int bcol = (tx << 3) ^ swk;
            ulonglong2 bv0 = *(const ulonglong2*)&Ws[kk][bcol];
            ulonglong2 bv1 = *(const ulonglong2*)&Ws[kk][bcol + 4];
            ull a2[4] = { pack2(a4.x, a4.x), pack2(a4.y, a4.y),
                          pack2(a4.z, a4.z), pack2(a4.w, a4.w) };
            ull b2[4] = { bv0.x, bv0.y, bv1.x, bv1.y };
#pragma unroll
            for (int i = 0; i < 4; i++)
#pragma unroll
                for (int j = 0; j < 4; j++) fma2(acc[i][j], a2[i], b2[j]);
        }
        __syncthreads();
    }

    if (kt_mode) {
#pragma unroll
        for (int i = 0; i < 4; i++) {
            int mm = (ty << 2) + i;
#pragma unroll
            for (int j = 0; j < 4; j++) {
                float2 v = unpack2(acc[i][j]);
                int nn = (tx << 3) + j * 2;
                T[nn][mm]     = v.x + bias[n0 + nn];
                T[nn + 1][mm] = v.y + bias[n0 + nn + 1];
            }
        }
        __syncthreads();
        const int bb  = m0 >> 10;
        const int ml0 = m0 & 1023;
#pragma unroll
        for (int r = 0; r < 8; r++) {
            int idx = tid + r * 256;
            int row = idx >> 4;
            int c4  = (idx & 15) << 2;
            float4 v;
            v.x = T[row][c4]; v.y = T[row][c4 + 1];
            v.z = T[row][c4 + 2]; v.w = T[row][c4 + 3];
            *(float4*)&out[((size_t)(bb << 8) + n0 + row) * ML_ + ml0 + c4] = v;
        }
    } else {
#pragma unroll
        for (int i = 0; i < 4; i++) {
            int m = m0 + (ty << 2) + i;
#pragma unroll
            for (int j = 0; j < 4; j++) {
                float2 v = unpack2(acc[i][j]);
                int na = n0 + (tx << 3) + j * 2;
                float2 o = make_float2(v.x + bias[na], v.y + bias[na + 1]);
                *(float2*)&out[(size_t)m * H_ + na] = o;
            }
        }
    }
}

// ---------- K1: fused logits + softmax + AV, LQG=8 ----------
// grid (QL/8=16, B), 512 threads.
// Phase B: thread owns m = 2t, 2t+1 for 8 q rows.
// Phase C: thread owns KS cols (2c, 2c+1), m-half mh; smem combine.
#define LQG 8
__global__ __launch_bounds__(512) void attn_fused_kernel(
    const float* __restrict__ qbuf,    // [B*QL][H]
    const float* __restrict__ kT,      // [B][H][ML]
    const float* __restrict__ memory,  // [B][ML][KS]
    const void* __restrict__ mask_raw, // [B][ML]
    const float* __restrict__ wl, const float* __restrict__ blp,
    float* __restrict__ out_attn,      // [B][QL][KS]
    float* __restrict__ out_w)         // [B*QL][ML]
{
    __shared__ float q_s[LQG][H_];                    // 8 KB
    __shared__ float wl_s[H_];                        // 1 KB
    __shared__ __align__(16) float w_s[ML_][LQG];     // 32 KB (aliased by ps later)
    __shared__ float red_s[LQG * 16];

    const int t  = threadIdx.x;
    const int b  = blockIdx.y;
    const int q0 = blockIdx.x * LQG;

    for (int i = t; i < LQG * H_; i += 512)
        q_s[i >> 8][i & 255] = qbuf[(size_t)(b * QL_ + q0) * H_ + i];
    if (t < H_) wl_s[t] = wl[t];
    __syncthreads();

    const float* kb = kT + (size_t)b * H_ * ML_;
    const int m0 = t * 2;

    // ---- phase B: logits (MUFU.TANH-bound) ----
    float lg[LQG][2];
#pragma unroll
    for (int g = 0; g < LQG; g++) { lg[g][0] = 0.f; lg[g][1] = 0.f; }

#pragma unroll 2
    for (int h = 0; h < H_; h++) {
        float2 kv = *(const float2*)&kb[(size_t)h * ML_ + m0];
        float wlh = wl_s[h];
#pragma unroll
        for (int g = 0; g < LQG; g++) {
            float qv = q_s[g][h];
            lg[g][0] = fmaf(wlh, fast_tanh(qv + kv.x), lg[g][0]);
            lg[g][1] = fmaf(wlh, fast_tanh(qv + kv.y), lg[g][1]);
        }
    }

    bool mk0, mk1;
    {
        const int mode = g_mask_mode;
        const int idx = b * ML_ + m0;
        if (mode == 1) {
            const int* mi = (const int*)mask_raw;
            mk0 = mi[idx] != 0; mk1 = mi[idx + 1] != 0;
        } else if (mode == 2) {
            const float* mf = (const float*)mask_raw;
            mk0 = mf[idx] != 0.f; mk1 = mf[idx + 1] != 0.f;
        } else {
            const unsigned char* mu = (const unsigned char*)mask_raw;
            mk0 = mu[idx] != 0; mk1 = mu[idx + 1] != 0;
        }
    }
    const float blv = *blp;
#pragma unroll
    for (int g = 0; g < LQG; g++) {
        lg[g][0] = mk0 ? -1e18f : (lg[g][0] + blv);
        lg[g][1] = mk1 ? -1e18f : (lg[g][1] + blv);
    }

    // ---- softmax (16 warps, full ML row in block) ----
    const int lane = t & 31, wid = t >> 5;
    float r[LQG];
#pragma unroll
    for (int g = 0; g < LQG; g++) r[g] = fmaxf(lg[g][0], lg[g][1]);
#pragma unroll
    for (int o = 16; o > 0; o >>= 1)
#pragma unroll
        for (int g = 0; g < LQG; g++)
            r[g] = fmaxf(r[g], __shfl_xor_sync(0xffffffffu, r[g], o));
    if (lane == 0) {
#pragma unroll
        for (int g = 0; g < LQG; g++) red_s[g * 16 + wid] = r[g];
    }
    __syncthreads();
    float gmax[LQG];
#pragma unroll
    for (int g = 0; g < LQG; g++) {
        float mx = red_s[g * 16];
#pragma unroll
        for (int j = 1; j < 16; j++) mx = fmaxf(mx, red_s[g * 16 + j]);
        gmax[g] = mx;
    }
    __syncthreads();

    float e0[LQG], e1[LQG];
#pragma unroll
    for (int g = 0; g < LQG; g++) {
        e0[g] = __expf(lg[g][0] - gmax[g]);
        e1[g] = __expf(lg[g][1] - gmax[g]);
        r[g]  = e0[g] + e1[g];
    }
#pragma unroll
    for (int o = 16; o > 0; o >>= 1)
#pragma unroll
        for (int g = 0; g < LQG; g++)
            r[g] += __shfl_xor_sync(0xffffffffu, r[g], o);
    if (lane == 0) {
#pragma unroll
        for (int g = 0; g < LQG; g++) red_s[g * 16 + wid] = r[g];
    }
    __syncthreads();
#pragma unroll
    for (int g = 0; g < LQG; g++) {
        float s = red_s[g * 16];
#pragma unroll
        for (int j = 1; j < 16; j++) s += red_s[g * 16 + j];
        float inv = 1.0f / s;
        float w0v = e0[g] * inv;
        float w1v = e1[g] * inv;
        w_s[m0][g]     = w0v;
        w_s[m0 + 1][g] = w1v;
        *(float2*)&out_w[(size_t)(b * QL_ + q0 + g) * ML_ + m0] = make_float2(w0v, w1v);
    }
    __syncthreads();

    // ---- phase C: attns = weights @ memory ----
    // thread: cols (2c, 2c+1), m-half mh (512 m each); LDG.64 per iter.
    const int mh = t >> 8;        // 0 / 1
    const int c  = t & 255;
    const float* memb = memory + (size_t)b * ML_ * KS_
                        + (size_t)mh * 512 * KS_ + 2 * c;
    ull acc2[LQG] = {0ull, 0ull, 0ull, 0ull, 0ull, 0ull, 0ull, 0ull};
#pragma unroll 4
    for (int m = 0; m < 512; m++) {
        ull mv2 = *(const ull*)&memb[(size_t)m * KS_];           // 2 cols, coalesced
        float4 wv0 = *(const float4*)&w_s[mh * 512 + m][0];      // broadcast LDS.128
        float4 wv1 = *(const float4*)&w_s[mh * 512 + m][4];
        fma2(acc2[0], pack2(wv0.x, wv0.x), mv2);
        fma2(acc2[1], pack2(wv0.y, wv0.y), mv2);
        fma2(acc2[2], pack2(wv0.z, wv0.z), mv2);
        fma2(acc2[3], pack2(wv0.w, wv0.w), mv2);
        fma2(acc2[4], pack2(wv1.x, wv1.x), mv2);
        fma2(acc2[5], pack2(wv1.y, wv1.y), mv2);
        fma2(acc2[6], pack2(wv1.z, wv1.z), mv2);
        fma2(acc2[7], pack2(wv1.w, wv1.w), mv2);
    }

    // combine halves via smem (alias w_s): stride 17 -> conflict-free
    __syncthreads();                       // everyone done reading w_s
    float* ps = &w_s[0][0];                // 256 x 17 floats used
    if (mh == 1) {
#pragma unroll
        for (int g = 0; g < LQG; g++) {
            float2 v = unpack2(acc2[g]);
            ps[c * 17 + g * 2]     = v.x;
            ps[c * 17 + g * 2 + 1] = v.y;
        }
    }
    __syncthreads();
    if (mh == 0) {
#pragma unroll
        for (int g = 0; g < LQG; g++) {
            float2 v = unpack2(acc2[g]);
            v.x += ps[c * 17 + g * 2];
            v.y += ps[c * 17 + g * 2 + 1];
            *(float2*)&out_attn[(size_t)(b * QL_ + q0 + g) * KS_ + 2 * c] = v;
        }
    }
}

// ---------- launch ----------
extern "C" void kernel_launch(void* const* d_in, const int* in_sizes, int n_in,
                              void* d_out, int out_size) {
    const float* query  = (const float*)d_in[0];
    const float* memory = (const float*)d_in[1];
    const void*  mask   = d_in[2];
    const float* Wq = (const float*)d_in[3];
    const float* bq = (const float*)d_in[4];
    const float* Wk = (const float*)d_in[5];
    const float* bk = (const float*)d_in[6];
    const float* wl = (const float*)d_in[7];
    const float* bl = (const float*)d_in[8];

    float* out = (float*)d_out;
    float *qptr, *kptr, *wfb;
    cudaGetSymbolAddress((void**)&qptr, g_q);
    cudaGetSymbolAddress((void**)&kptr, g_kT);
    cudaGetSymbolAddress((void**)&wfb, g_wfallback);

    // output = concat(attns [B,QL,KS], weights [B,QL,ML])
    float* out_attn = out;
    float* out_w = (out_size >= B_ * QL_ * KS_ + B_ * QL_ * ML_)
                       ? (out + B_ * QL_ * KS_) : wfb;

    // merged detect + q-proj + k-proj: 1 + 2*(16 + 128) blocks
    proj_kernel<<<1 + 2 * (16 + 128), 256>>>(
        query, Wq, bq, qptr, memory, Wk, bk, kptr,
        (const unsigned char*)mask);
    attn_fused_kernel<<<dim3(QL_ / LQG, B_), 512>>>(
        qptr, kptr, memory, mask, wl, bl, out_attn, out_w);
}

// round 17
// speedup vs baseline: 1.5145x; 1.1709x over previous
#include <cuda_runtime.h>
#include <cstdint>

// Problem constants
#define B_   8
#define QL_  128
#define ML_  1024
#define KS_  512
#define H_   256

typedef unsigned long long ull;

// ---------- Blackwell packed-f32 helpers ----------
__device__ __forceinline__ ull pack2(float x, float y) {
    ull r; asm("mov.b64 %0, {%1,%2};" : "=l"(r) : "f"(x), "f"(y)); return r;
}
__device__ __forceinline__ void fma2(ull &d, ull a, ull b) {
    asm("fma.rn.f32x2 %0, %1, %2, %0;" : "+l"(d) : "l"(a), "l"(b));
}
__device__ __forceinline__ float2 unpack2(ull v) {
    float2 f; asm("mov.b64 {%0,%1}, %2;" : "=f"(f.x), "=f"(f.y) : "l"(v)); return f;
}
__device__ __forceinline__ float fast_tanh(float x) {
    float r; asm("tanh.approx.f32 %0, %1;" : "=f"(r) : "f"(x)); return r;
}

// XOR swizzle for conflict-free GEMM smem staging (bits >=3 only)
#define SWZ(r) (((r) & 12) << 1)

// ---------- scratch ----------
__device__ float g_q[B_ * QL_ * H_];          // [B*QL][H]
__device__ float g_kT[B_ * H_ * ML_];         // [B][H][ML]
__device__ float g_wfallback[B_ * QL_ * ML_];
__device__ int   g_mask_mode;                 // 0=u8, 1=i32, 2=f32

// ---------- merged kernel: mask-detect (block 0) + q-proj + k-proj ----------
// grid: 1 + 2*(16 + 128) = 289 blocks, 256 threads.
#define GBM 64
#define GBN 128
#define GBK 16

__global__ __launch_bounds__(256) void proj_kernel(
    const float* __restrict__ query, const float* __restrict__ Wq,
    const float* __restrict__ bq, float* __restrict__ qout,
    const float* __restrict__ memory, const float* __restrict__ Wk,
    const float* __restrict__ bk, float* __restrict__ kout,
    const unsigned char* __restrict__ mask_bytes)
{
    const int bid = blockIdx.x;
    const int tid = threadIdx.x;

    if (bid == 0) {
        // ---- mask dtype auto-detection ----
        __shared__ int viol[3];
        if (tid < 3) viol[tid] = 0;
        __syncthreads();
        int v_u8 = 0, v_i32 = 0, v_f32 = 0;
        for (int i = tid; i < B_ * ML_; i += 256) {
            unsigned char b = mask_bytes[i];
            int r = i & 3;
            if (b > 1) v_u8++;
            if (r != 0 && b != 0) v_i32++;
            if (r == 0 || r == 1) { if (b != 0) v_f32++; }
            else if (r == 2)      { if (b != 0 && b != 128) v_f32++; }
            else                  { if (b != 0 && b != 63)  v_f32++; }
        }
        atomicAdd(&viol[0], v_u8);
        atomicAdd(&viol[1], v_i32);
        atomicAdd(&viol[2], v_f32);
        __syncthreads();
        if (tid == 0) {
            int mode;
            if      (viol[1] == 0) mode = 1;
            else if (viol[2] == 0) mode = 2;
            else                   mode = 0;
            g_mask_mode = mode;
        }
        return;
    }

    __shared__ float As[GBK][GBM];
    __shared__ float Ws[GBK][GBN];
    __shared__ float T[GBN][GBM + 1];

    const int tile = bid - 1;
    const int nt = tile & 1;
    const int mt = tile >> 1;
    const int kt_mode = (mt >= 16);
    const float* A    = kt_mode ? memory : query;
    const float* W    = kt_mode ? Wk : Wq;
    const float* bias = kt_mode ? bk : bq;
    float* out        = kt_mode ? kout : qout;
    const int m0 = (kt_mode ? (mt - 16) : mt) * GBM;
    const int n0 = nt * GBN;
    const int K = 512;

    const int tx = tid & 15;
    const int ty = tid >> 4;

    ull acc[4][4];
#pragma unroll
    for (int i = 0; i < 4; i++)
#pragma unroll
        for (int j = 0; j < 4; j++) acc[i][j] = 0ull;

    const int arow = tid >> 2;
    const int acol = (tid & 3) << 2;
    const int sws  = SWZ(acol);
    const int arow_s   = arow ^ sws;
    const int arow64_s = (arow + 64) ^ sws;

    float4 av = *(const float4*)&A[(size_t)(m0 + arow) * K + acol];
    float4 w0 = *(const float4*)&W[(size_t)(n0 + arow) * K + acol];
    float4 w1 = *(const float4*)&W[(size_t)(n0 + arow + 64) * K + acol];

    for (int k0 = 0; k0 < K; k0 += GBK) {
        As[acol + 0][arow_s] = av.x; As[acol + 1][arow_s] = av.y;
        As[acol + 2][arow_s] = av.z; As[acol + 3][arow_s] = av.w;
        Ws[acol + 0][arow_s] = w0.x; Ws[acol + 1][arow_s] = w0.y;
        Ws[acol + 2][arow_s] = w0.z; Ws[acol + 3][arow_s] = w0.w;
        Ws[acol + 0][arow64_s] = w1.x; Ws[acol + 1][arow64_s] = w1.y;
        Ws[acol + 2][arow64_s] = w1.z; Ws[acol + 3][arow64_s] = w1.w;
        __syncthreads();

        if (k0 + GBK < K) {
            av = *(const float4*)&A[(size_t)(m0 + arow) * K + k0 + GBK + acol];
            w0 = *(const float4*)&W[(size_t)(n0 + arow) * K + k0 + GBK + acol];
            w1 = *(const float4*)&W[(size_t)(n0 + arow + 64) * K + k0 + GBK + acol];
        }

#pragma unroll
        for (int kk = 0; kk < GBK; kk++) {
            const int swk = SWZ(kk);
            float4 a4 = *(const float4*)&As[kk][(ty << 2) ^ swk];
            const int bcol = (tx << 3) ^ swk;
            ulonglong2 bv0 = *(const ulonglong2*)&Ws[kk][bcol];
            ulonglong2 bv1 = *(const ulonglong2*)&Ws[kk][bcol + 4];
            ull a2[4] = { pack2(a4.x, a4.x), pack2(a4.y, a4.y),
                          pack2(a4.z, a4.z), pack2(a4.w, a4.w) };
            ull b2[4] = { bv0.x, bv0.y, bv1.x, bv1.y };
#pragma unroll
            for (int i = 0; i < 4; i++)
#pragma unroll
                for (int j = 0; j < 4; j++) fma2(acc[i][j], a2[i], b2[j]);
        }
        __syncthreads();
    }

    if (kt_mode) {
#pragma unroll
        for (int i = 0; i < 4; i++) {
            int mm = (ty << 2) + i;
#pragma unroll
            for (int j = 0; j < 4; j++) {
                float2 v = unpack2(acc[i][j]);
                int nn = (tx << 3) + j * 2;
                T[nn][mm]     = v.x + bias[n0 + nn];
                T[nn + 1][mm] = v.y + bias[n0 + nn + 1];
            }
        }
        __syncthreads();
        const int bb  = m0 >> 10;
        const int ml0 = m0 & 1023;
#pragma unroll
        for (int r = 0; r < 8; r++) {
            int idx = tid + r * 256;
            int row = idx >> 4;
            int c4  = (idx & 15) << 2;
            float4 v;
            v.x = T[row][c4]; v.y = T[row][c4 + 1];
            v.z = T[row][c4 + 2]; v.w = T[row][c4 + 3];
            *(float4*)&out[((size_t)(bb << 8) + n0 + row) * ML_ + ml0 + c4] = v;
        }
    } else {
#pragma unroll
        for (int i = 0; i < 4; i++) {
            int m = m0 + (ty << 2) + i;
#pragma unroll
            for (int j = 0; j < 4; j++) {
                float2 v = unpack2(acc[i][j]);
                int na = n0 + (tx << 3) + j * 2;
                float2 o = make_float2(v.x + bias[na], v.y + bias[na + 1]);
                *(float2*)&out[(size_t)m * H_ + na] = o;
            }
        }
    }
}

// ---------- K1: fused logits + softmax + AV, LQG=4 (R11 config: 2 blocks/SM overlap) ----------
// grid (QL/4=32, B), 512 threads.
#define LQG 4
__global__ __launch_bounds__(512) void attn_fused_kernel(
    const float* __restrict__ qbuf,    // [B*QL][H]
    const float* __restrict__ kT,      // [B][H][ML]
    const float* __restrict__ memory,  // [B][ML][KS]
    const void* __restrict__ mask_raw, // [B][ML]
    const float* __restrict__ wl, const float* __restrict__ blp,
    float* __restrict__ out_attn,      // [B][QL][KS]
    float* __restrict__ out_w)         // [B*QL][ML]
{
    __shared__ float q_s[LQG][H_];                    // 4 KB
    __shared__ float wl_s[H_];                        // 1 KB
    __shared__ __align__(16) float w_s[ML_][LQG];     // 16 KB (aliased by ps later)
    __shared__ float red_s[LQG * 16];

    const int t  = threadIdx.x;
    const int b  = blockIdx.y;
    const int q0 = blockIdx.x * LQG;

    for (int i = t; i < LQG * H_; i += 512)
        q_s[i >> 8][i & 255] = qbuf[(size_t)(b * QL_ + q0) * H_ + i];
    if (t < H_) wl_s[t] = wl[t];
    __syncthreads();

    const float* kb = kT + (size_t)b * H_ * ML_;
    const int m0 = t * 2;

    // ---- phase B: logits (MUFU.TANH-bound) ----
    float lg[LQG][2];
#pragma unroll
    for (int g = 0; g < LQG; g++) { lg[g][0] = 0.f; lg[g][1] = 0.f; }

#pragma unroll 4
    for (int h = 0; h < H_; h++) {
        float2 kv = *(const float2*)&kb[(size_t)h * ML_ + m0];
        float wlh = wl_s[h];
#pragma unroll
        for (int g = 0; g < LQG; g++) {
            float qv = q_s[g][h];
            lg[g][0] = fmaf(wlh, fast_tanh(qv + kv.x), lg[g][0]);
            lg[g][1] = fmaf(wlh, fast_tanh(qv + kv.y), lg[g][1]);
        }
    }

    bool mk0, mk1;
    {
        const int mode = g_mask_mode;
        const int idx = b * ML_ + m0;
        if (mode == 1) {
            const int* mi = (const int*)mask_raw;
            mk0 = mi[idx] != 0; mk1 = mi[idx + 1] != 0;
        } else if (mode == 2) {
            const float* mf = (const float*)mask_raw;
            mk0 = mf[idx] != 0.f; mk1 = mf[idx + 1] != 0.f;
        } else {
            const unsigned char* mu = (const unsigned char*)mask_raw;
            mk0 = mu[idx] != 0; mk1 = mu[idx + 1] != 0;
        }
    }
    const float blv = *blp;
#pragma unroll
    for (int g = 0; g < LQG; g++) {
        lg[g][0] = mk0 ? -1e18f : (lg[g][0] + blv);
        lg[g][1] = mk1 ? -1e18f : (lg[g][1] + blv);
    }

    // ---- softmax (16 warps, full ML row in block) ----
    const int lane = t & 31, wid = t >> 5;
    float r[LQG];
#pragma unroll
    for (int g = 0; g < LQG; g++) r[g] = fmaxf(lg[g][0], lg[g][1]);
#pragma unroll
    for (int o = 16; o > 0; o >>= 1)
#pragma unroll
        for (int g = 0; g < LQG; g++)
            r[g] = fmaxf(r[g], __shfl_xor_sync(0xffffffffu, r[g], o));
    if (lane == 0) {
#pragma unroll
        for (int g = 0; g < LQG; g++) red_s[g * 16 + wid] = r[g];
    }
    __syncthreads();
    float gmax[LQG];
#pragma unroll
    for (int g = 0; g < LQG; g++) {
        float mx = red_s[g * 16];
#pragma unroll
        for (int j = 1; j < 16; j++) mx = fmaxf(mx, red_s[g * 16 + j]);
        gmax[g] = mx;
    }
    __syncthreads();

    float e0[LQG], e1[LQG];
#pragma unroll
    for (int g = 0; g < LQG; g++) {
        e0[g] = __expf(lg[g][0] - gmax[g]);
        e1[g] = __expf(lg[g][1] - gmax[g]);
        r[g]  = e0[g] + e1[g];
    }
#pragma unroll
    for (int o = 16; o > 0; o >>= 1)
#pragma unroll
        for (int g = 0; g < LQG; g++)
            r[g] += __shfl_xor_sync(0xffffffffu, r[g], o);
    if (lane == 0) {
#pragma unroll
        for (int g = 0; g < LQG; g++) red_s[g * 16 + wid] = r[g];
    }
    __syncthreads();
#pragma unroll
    for (int g = 0; g < LQG; g++) {
        float s = red_s[g * 16];
#pragma unroll
        for (int j = 1; j < 16; j++) s += red_s[g * 16 + j];
        float inv = 1.0f / s;
        float w0v = e0[g] * inv;
        float w1v = e1[g] * inv;
        w_s[m0][g]     = w0v;
        w_s[m0 + 1][g] = w1v;
        *(float2*)&out_w[(size_t)(b * QL_ + q0 + g) * ML_ + m0] = make_float2(w0v, w1v);
    }
    __syncthreads();

    // ---- phase C: attns = weights @ memory ----
    // thread: cols (2c, 2c+1), m-half mh (512 m each); streaming LDG.64 per iter.
    const int mh = t >> 8;        // 0 / 1
    const int c  = t & 255;
    const float* memb = memory + (size_t)b * ML_ * KS_
                        + (size_t)mh * 512 * KS_ + 2 * c;
    ull acc2[LQG] = {0ull, 0ull, 0ull, 0ull};
#pragma unroll 8
    for (int m = 0; m < 512; m++) {
        ull mv2 = __ldcs((const ull*)&memb[(size_t)m * KS_]);   // 2 cols, streaming
        float4 wv = *(const float4*)&w_s[mh * 512 + m][0];      // broadcast LDS.128
        fma2(acc2[0], pack2(wv.x, wv.x), mv2);
        fma2(acc2[1], pack2(wv.y, wv.y), mv2);
        fma2(acc2[2], pack2(wv.z, wv.z), mv2);
        fma2(acc2[3], pack2(wv.w, wv.w), mv2);
    }

    // combine halves: mh=1 publishes partials via smem (alias w_s), mh=0 sums+stores
    __syncthreads();                       // everyone done reading w_s
    float* ps = &w_s[0][0];                // 256 x 9 floats, conflict-free stride
    if (mh == 1) {
#pragma unroll
        for (int g = 0; g < LQG; g++) {
            float2 v = unpack2(acc2[g]);
            ps[c * 9 + g * 2]     = v.x;
            ps[c * 9 + g * 2 + 1] = v.y;
        }
    }
    __syncthreads();
    if (mh == 0) {
#pragma unroll
        for (int g = 0; g < LQG; g++) {
            float2 v = unpack2(acc2[g]);
            v.x += ps[c * 9 + g * 2];
            v.y += ps[c * 9 + g * 2 + 1];
            *(float2*)&out_attn[(size_t)(b * QL_ + q0 + g) * KS_ + 2 * c] = v;
        }
    }
}

// ---------- launch ----------
extern "C" void kernel_launch(void* const* d_in, const int* in_sizes, int n_in,
                              void* d_out, int out_size) {
    const float* query  = (const float*)d_in[0];
    const float* memory = (const float*)d_in[1];
    const void*  mask   = d_in[2];
    const float* Wq = (const float*)d_in[3];
    const float* bq = (const float*)d_in[4];
    const float* Wk = (const float*)d_in[5];
    const float* bk = (const float*)d_in[6];
    const float* wl = (const float*)d_in[7];
    const float* bl = (const float*)d_in[8];

    float* out = (float*)d_out;
    float *qptr, *kptr, *wfb;
    cudaGetSymbolAddress((void**)&qptr, g_q);
    cudaGetSymbolAddress((void**)&kptr, g_kT);
    cudaGetSymbolAddress((void**)&wfb, g_wfallback);

    // output = concat(attns [B,QL,KS], weights [B,QL,ML])
    float* out_attn = out;
    float* out_w = (out_size >= B_ * QL_ * KS_ + B_ * QL_ * ML_)
                       ? (out + B_ * QL_ * KS_) : wfb;

    // merged detect + q-proj + k-proj: 1 + 2*(16 + 128) blocks
    proj_kernel<<<1 + 2 * (16 + 128), 256>>>(
        query, Wq, bq, qptr, memory, Wk, bk, kptr,
        (const unsigned char*)mask);
    attn_fused_kernel<<<dim3(QL_ / LQG, B_), 512>>>(
        qptr, kptr, memory, mask, wl, bl, out_attn, out_w);
}